// round 12
// baseline (speedup 1.0000x reference)
#include <cuda_runtime.h>
#include <cuda_fp16.h>
#include <math.h>

#define BB 64
#define TT 2048
#define DD 128
#define UU 128
#define G3 384
#define NS 3

// ---------------- scratch (device globals: allocation-free) ----------------
__device__ float   g_GX[(size_t)TT * BB * G3];      // x@kernel + bias   [t][b][384]
__device__ float   g_PX[(size_t)TT * NS * BB * DD]; // x@sub_kernel_x    [t][r][128]
__device__ __half2 g_Rh2[64 * G3];                  // R packed: [ug][j]
__device__ __half2 g_skh2[NS * 64 * 128];           // skh packed: [n][og][i]
__device__ __half2 g_dwh2[NS * 64 * 128];           // dw packed:  [n][ig][o]
__device__ __half2 g_awh2[192 * 128];               // aw packed:  [kg][j]

// ---------------- weight packing: reduction-major half2 --------------------
__global__ void pack_weights(const float* __restrict__ R,
                             const float* __restrict__ skh,
                             const float* __restrict__ dw,
                             const float* __restrict__ aw) {
    int idx = blockIdx.x * blockDim.x + threadIdx.x;
    if (idx < 24576) {                      // R: 64 x 384
        int ug = idx / G3, j = idx % G3;
        g_Rh2[idx] = __floats2half2_rn(R[(2*ug)*G3 + j], R[(2*ug+1)*G3 + j]);
    } else if (idx < 49152) {               // skh: 3 x 64 x 128
        int e = idx - 24576;
        int n = e / 8192, rem = e % 8192, og = rem / 128, i = rem % 128;
        const float* p = skh + n * 16384;
        g_skh2[e] = __floats2half2_rn(p[(2*og)*128 + i], p[(2*og+1)*128 + i]);
    } else if (idx < 73728) {               // dw: 3 x 64 x 128
        int e = idx - 49152;
        int n = e / 8192, rem = e % 8192, ig = rem / 128, o = rem % 128;
        const float* p = dw + n * 16384;
        g_dwh2[e] = __floats2half2_rn(p[(2*ig)*128 + o], p[(2*ig+1)*128 + o]);
    } else if (idx < 98304) {               // aw: 192 x 128
        int e = idx - 73728;
        int kg = e / 128, j = e % 128;
        g_awh2[e] = __floats2half2_rn(aw[(2*kg)*128 + j], aw[(2*kg+1)*128 + j]);
    }
}

// ---------------- parallel precompute of x-only terms (fp32) ---------------
__global__ void __launch_bounds__(256) precompute_kernel(
    const float* __restrict__ x, const float* __restrict__ K,
    const float* __restrict__ skx, const float* __restrict__ bias)
{
    __shared__ float4 xs4[BB * 32];                    // x[:,t,:] 64x128 = 32KB
    int t = blockIdx.x;
    int w = blockIdx.y;
    int tid = threadIdx.x;

    const float4* xg = (const float4*)x;
    #pragma unroll
    for (int q = tid; q < BB * 32; q += 256) {
        int bb = q >> 5, dq = q & 31;
        xs4[q] = xg[(size_t)(bb * TT + t) * 32 + dq];
    }
    __syncthreads();

    int jq = tid & 31;
    int bq = tid >> 5;
    int c  = 4 * jq;
    const float* xsf = (const float*)xs4;

    const float* W;
    int wstride;
    if (w < 3) { W = K + w * 128 + c; wstride = G3; }
    else       { W = skx + (w - 3) * 16384 + c; wstride = 128; }

    float acc[8][4];
    #pragma unroll
    for (int bi = 0; bi < 8; bi++)
        #pragma unroll
        for (int q = 0; q < 4; q++) acc[bi][q] = 0.f;

    #pragma unroll 4
    for (int d = 0; d < 128; d++) {
        float4 wv = *(const float4*)(W + (size_t)d * wstride);
        #pragma unroll
        for (int bi = 0; bi < 8; bi++) {
            float xv = xsf[(8 * bq + bi) * 128 + d];
            acc[bi][0] = fmaf(xv, wv.x, acc[bi][0]);
            acc[bi][1] = fmaf(xv, wv.y, acc[bi][1]);
            acc[bi][2] = fmaf(xv, wv.z, acc[bi][2]);
            acc[bi][3] = fmaf(xv, wv.w, acc[bi][3]);
        }
    }

    if (w < 3) {
        float4 bv = *(const float4*)(bias + w * 128 + c);
        #pragma unroll
        for (int bi = 0; bi < 8; bi++) {
            int b = 8 * bq + bi;
            float4 r = make_float4(acc[bi][0] + bv.x, acc[bi][1] + bv.y,
                                   acc[bi][2] + bv.z, acc[bi][3] + bv.w);
            *(float4*)&g_GX[((size_t)t * BB + b) * G3 + w * 128 + c] = r;
        }
    } else {
        #pragma unroll
        for (int bi = 0; bi < 8; bi++) {
            int b = 8 * bq + bi;
            *(float4*)&g_PX[((size_t)t * (NS * BB) + (w - 3) * BB + b) * 128 + c] =
                make_float4(acc[bi][0], acc[bi][1], acc[bi][2], acc[bi][3]);
        }
    }
}

// ---------------- sequential recurrence: 64 independent chains -------------
struct __align__(16) SeqSmem {
    __half2 dw[NS * 64 * 128];   // 98304 B
    __half2 aw[192 * 128];       // 98304 B
    __half2 h2[64];
    __half2 s2[192];
    __half2 agg2[192];
    __half2 sub2[192];
    float   g[G3];
    float   tcv[128];
};

__device__ __forceinline__ float sigm_fast(float v) {
    return __fdividef(1.f, 1.f + __expf(-v));
}
__device__ __forceinline__ float tanh_fast(float v) {
    return 1.f - __fdividef(2.f, __expf(2.f * v) + 1.f);
}
__device__ __forceinline__ __half2 h2_of(unsigned u) {
    return *reinterpret_cast<__half2*>(&u);
}

// NBLK*32-MAC dot: 4 independent half2 chains, folded to fp32 every 32 MACs.
template <int WS, int NBLK>
__device__ __forceinline__ float dot_h2(const __half2* __restrict__ w,
                                        const uint4* __restrict__ acts)
{
    float f0 = 0.f, f1 = 0.f;
    #pragma unroll
    for (int blk = 0; blk < NBLK; blk++) {
        __half2 z = __float2half2_rn(0.f);
        __half2 c0 = z, c1 = z, c2 = z, c3 = z;
        #pragma unroll
        for (int i = 0; i < 4; i++) {
            uint4 A = acts[4 * blk + i];
            const __half2* wp = w + (size_t)(16 * blk + 4 * i) * WS;
            c0 = __hfma2(wp[0],      h2_of(A.x), c0);
            c1 = __hfma2(wp[1 * WS], h2_of(A.y), c1);
            c2 = __hfma2(wp[2 * WS], h2_of(A.z), c2);
            c3 = __hfma2(wp[3 * WS], h2_of(A.w), c3);
        }
        __half2 sc = __hadd2(__hadd2(c0, c1), __hadd2(c2, c3));
        float2 ff = __half22float2(sc);
        f0 += ff.x;
        f1 += ff.y;
    }
    return f0 + f1;
}

__global__ void __launch_bounds__(768, 1) seq_kernel(
    const float* __restrict__ stk, const float* __restrict__ db,
    const float* __restrict__ ab, float* __restrict__ out)
{
    extern __shared__ char smem_raw[];
    SeqSmem& sh = *reinterpret_cast<SeqSmem*>(smem_raw);

    int tid = threadIdx.x;
    int b   = blockIdx.x;

    // stage-A mapping (gates || agg), as validated in R10
    int grp  = tid / 384;               // 0: gates, 1: agg_in
    int t384 = tid - grp * 384;
    int kA   = t384 >> 7;
    int colA = t384 & 127;
    int rA   = 3 * b + kA;
    int nA   = rA >> 6;

    // stage-B mapping: thread = 2*o + p  (o: dense output 0..383, p: split half)
    int oB   = tid >> 1;
    int pB   = tid & 1;
    int kB   = oB >> 7;
    int colB = oB & 127;
    int nB   = (3 * b + kB) >> 6;

    // stage-C mapping: thread = 4*j + p (j: output 0..127, p: split quarter), tid<512
    int jC = tid >> 2;
    int pC = tid & 3;

    // bulk-copy SMEM-resident weights (dw, aw)
    {
        const uint4* src_dw = (const uint4*)g_dwh2;
        const uint4* src_aw = (const uint4*)g_awh2;
        uint4* dst_dw = (uint4*)sh.dw;
        uint4* dst_aw = (uint4*)sh.aw;
        for (int i = tid; i < 6144; i += 768) {
            dst_dw[i] = src_dw[i];
            dst_aw[i] = src_aw[i];
        }
    }
    // per-thread constants
    float db_r = db[nB * 128 + colB];
    float rh_r = stk[nB * 256 + colB];
    float rx_r = stk[nB * 256 + 128 + colB];
    float ab_r = (tid < 512) ? ab[jC] : 0.f;
    float s_reg = 0.f, c_reg = 0.f;

    if (tid < 64)  sh.h2[tid] = __float2half2_rn(0.f);
    if (tid < 192) sh.s2[tid] = __float2half2_rn(0.f);
    __syncthreads();

    // stage-A weight pointers
    const __half2* Rp = g_Rh2 + t384;               // gates (grp0), stride G3
    const __half2* Sp = g_skh2 + nA * 8192 + colA;  // agg   (grp1), stride 128
    // stage-B weights (SMEM): output oB, reduction half pB
    const __half2* Dp = sh.dw + nB * 8192 + (pB << 5) * 128 + colB;
    // stage-C weights (SMEM): output jC, reduction quarter pC (48 pair-rows each)
    const __half2* Ap = sh.aw + (pC * 48) * 128 + jC;

    // x-term stream (stride per t is 24576 floats for both arrays)
    const float* xp = (grp == 0) ? (g_GX + (size_t)b * G3 + t384)
                                 : (g_PX + (size_t)rA * 128 + colA);
    float xt = __ldcs(xp);

    const uint4* hq  = (const uint4*)sh.h2;
    const uint4* sq  = (const uint4*)(sh.s2 + (kA << 6));
    const uint4* aqB = (const uint4*)(sh.agg2 + (kB << 6)) + (pB << 3);
    const uint4* bqC = (const uint4*)sh.sub2 + pC * 12;

    for (int t = 0; t < TT; t++) {
        int tn = (t + 1 < TT) ? (t + 1) : t;
        float xtN = __ldcs(xp + (size_t)tn * 24576);

        // ---- stage A: gates (warps 0-11) || agg_in (warps 12-23)
        if (grp == 0) {
            float gdot = dot_h2<G3, 4>(Rp, hq);
            sh.g[t384] = sigm_fast(xt + gdot);
        } else {
            float edot = dot_h2<128, 4>(Sp, sq);
            float aggv = xt + edot;
            float aggp = __shfl_xor_sync(0xffffffffu, aggv, 1);
            if (!(colA & 1))
                sh.agg2[(kA << 6) + (colA >> 1)] = __floats2half2_rn(aggv, aggp);
        }
        __syncthreads();

        // ---- stage B: dense (2-way split-K, shuffle combine) + s/c update
        {
            float pv = dot_h2<128, 2>(Dp, aqB);
            pv += __shfl_xor_sync(0xffffffffu, pv, 1);
            float so = fmaxf(pv + db_r, 0.f);
            s_reg = fmaf(rh_r, so, rx_r * s_reg);
            float so2 = __shfl_xor_sync(0xffffffffu, so, 2);
            float ss2 = __shfl_xor_sync(0xffffffffu, s_reg, 2);
            if (!(tid & 3)) {
                sh.sub2[oB >> 1] = __floats2half2_rn(so, so2);
                sh.s2[oB >> 1]   = __floats2half2_rn(s_reg, ss2);
            }
            if (tid < 128) {
                c_reg = fmaf(sh.g[128 + tid], c_reg,
                             sh.g[tid] * tanh_fast(sh.g[256 + tid]));
                sh.tcv[tid] = tanh_fast(c_reg);
            }
        }
        __syncthreads();

        // ---- stage C: agg_w (4-way split-K on tid<512, shuffle combine) + h
        if (tid < 512) {
            float v = dot_h2<128, 3>(Ap, bqC);
            v += __shfl_xor_sync(0xffffffffu, v, 1);
            v += __shfl_xor_sync(0xffffffffu, v, 2);
            float ov = sigm_fast(v + ab_r);
            float hv = ov * sh.tcv[jC];
            float hv2 = __shfl_xor_sync(0xffffffffu, hv, 4);
            if (!(tid & 3)) {
                if (!(tid & 7)) sh.h2[jC >> 1] = __floats2half2_rn(hv, hv2);
                __stcs(&out[((size_t)b * TT + t) * 128 + jC], hv);  // (B,T,U)
            }
        }
        xt = xtN;
        __syncthreads();
    }
}

// ---------------- launch ----------------------------------------------------
extern "C" void kernel_launch(void* const* d_in, const int* in_sizes, int n_in,
                              void* d_out, int out_size)
{
    const float* x    = (const float*)d_in[0];
    const float* K    = (const float*)d_in[1];
    const float* R    = (const float*)d_in[2];
    const float* bias = (const float*)d_in[3];
    const float* skx  = (const float*)d_in[4];
    const float* skh  = (const float*)d_in[5];
    const float* stk  = (const float*)d_in[6];
    const float* dw   = (const float*)d_in[7];
    const float* db   = (const float*)d_in[8];
    const float* aw   = (const float*)d_in[9];
    const float* ab   = (const float*)d_in[10];
    float* out = (float*)d_out;

    pack_weights<<<384, 256>>>(R, skh, dw, aw);

    dim3 pg(TT, 6);
    precompute_kernel<<<pg, 256>>>(x, K, skx, bias);

    cudaFuncSetAttribute(seq_kernel, cudaFuncAttributeMaxDynamicSharedMemorySize,
                         (int)sizeof(SeqSmem));
    seq_kernel<<<BB, 768, sizeof(SeqSmem)>>>(stk, db, ab, out);
}

// round 14
// speedup vs baseline: 1.5012x; 1.5012x over previous
#include <cuda_runtime.h>
#include <cuda_fp16.h>
#include <math.h>

#define BB 64
#define TT 2048
#define DD 128
#define UU 128
#define G3 384
#define NS 3

// padded SMEM weight row strides (in half2 units)
#define PWD 144   // dw rows: 144 = 16 mod 32 banks -> 2-way interleave conflict-free
#define PWA 136   // aw rows: 136 =  8 mod 32 banks -> 4-way interleave conflict-free
#define SAGG 104  // agg bucket stride (16B-aligned, = 8 mod 32 banks)
#define SSUB 52   // sub bucket stride (16B-aligned)

// ---------------- scratch (device globals: allocation-free) ----------------
__device__ float   g_GX[(size_t)TT * BB * G3];      // x@kernel + bias   [t][b][384]
__device__ float   g_PX[(size_t)TT * NS * BB * DD]; // x@sub_kernel_x    [t][r][128]
__device__ __half2 g_Rh2[64 * G3];                  // R packed: [ug][j]
__device__ __half2 g_skh2[NS * 64 * 128];           // skh packed: [n][og][i]
__device__ __half2 g_dwp[NS * 64 * PWD];            // dw packed+padded: [n][ig][o]
__device__ __half2 g_awp[192 * PWA];                // aw packed+padded: [kg][j]

// ---------------- weight packing: reduction-major half2 --------------------
__global__ void pack_weights(const float* __restrict__ R,
                             const float* __restrict__ skh,
                             const float* __restrict__ dw,
                             const float* __restrict__ aw) {
    int idx = blockIdx.x * blockDim.x + threadIdx.x;
    if (idx < 24576) {                      // R: 64 x 384
        int ug = idx / G3, j = idx % G3;
        g_Rh2[idx] = __floats2half2_rn(R[(2*ug)*G3 + j], R[(2*ug+1)*G3 + j]);
    } else if (idx < 49152) {               // skh: 3 x 64 x 128
        int e = idx - 24576;
        int n = e / 8192, rem = e % 8192, og = rem / 128, i = rem % 128;
        const float* p = skh + n * 16384;
        g_skh2[e] = __floats2half2_rn(p[(2*og)*128 + i], p[(2*og+1)*128 + i]);
    } else if (idx < 73728) {               // dw: 3 x 64 x 128 -> padded rows
        int e = idx - 49152;
        int n = e / 8192, rem = e % 8192, ig = rem / 128, o = rem % 128;
        const float* p = dw + n * 16384;
        g_dwp[n * (64 * PWD) + ig * PWD + o] =
            __floats2half2_rn(p[(2*ig)*128 + o], p[(2*ig+1)*128 + o]);
    } else if (idx < 98304) {               // aw: 192 x 128 -> padded rows
        int e = idx - 73728;
        int kg = e / 128, j = e % 128;
        g_awp[kg * PWA + j] =
            __floats2half2_rn(aw[(2*kg)*128 + j], aw[(2*kg+1)*128 + j]);
    }
}

// ---------------- parallel precompute of x-only terms (fp32) ---------------
__global__ void __launch_bounds__(256) precompute_kernel(
    const float* __restrict__ x, const float* __restrict__ K,
    const float* __restrict__ skx, const float* __restrict__ bias)
{
    __shared__ float4 xs4[BB * 32];                    // x[:,t,:] 64x128 = 32KB
    int t = blockIdx.x;
    int w = blockIdx.y;
    int tid = threadIdx.x;

    const float4* xg = (const float4*)x;
    #pragma unroll
    for (int q = tid; q < BB * 32; q += 256) {
        int bb = q >> 5, dq = q & 31;
        xs4[q] = xg[(size_t)(bb * TT + t) * 32 + dq];
    }
    __syncthreads();

    int jq = tid & 31;
    int bq = tid >> 5;
    int c  = 4 * jq;
    const float* xsf = (const float*)xs4;

    const float* W;
    int wstride;
    if (w < 3) { W = K + w * 128 + c; wstride = G3; }
    else       { W = skx + (w - 3) * 16384 + c; wstride = 128; }

    float acc[8][4];
    #pragma unroll
    for (int bi = 0; bi < 8; bi++)
        #pragma unroll
        for (int q = 0; q < 4; q++) acc[bi][q] = 0.f;

    #pragma unroll 4
    for (int d = 0; d < 128; d++) {
        float4 wv = *(const float4*)(W + (size_t)d * wstride);
        #pragma unroll
        for (int bi = 0; bi < 8; bi++) {
            float xv = xsf[(8 * bq + bi) * 128 + d];
            acc[bi][0] = fmaf(xv, wv.x, acc[bi][0]);
            acc[bi][1] = fmaf(xv, wv.y, acc[bi][1]);
            acc[bi][2] = fmaf(xv, wv.z, acc[bi][2]);
            acc[bi][3] = fmaf(xv, wv.w, acc[bi][3]);
        }
    }

    if (w < 3) {
        float4 bv = *(const float4*)(bias + w * 128 + c);
        #pragma unroll
        for (int bi = 0; bi < 8; bi++) {
            int b = 8 * bq + bi;
            float4 r = make_float4(acc[bi][0] + bv.x, acc[bi][1] + bv.y,
                                   acc[bi][2] + bv.z, acc[bi][3] + bv.w);
            *(float4*)&g_GX[((size_t)t * BB + b) * G3 + w * 128 + c] = r;
        }
    } else {
        #pragma unroll
        for (int bi = 0; bi < 8; bi++) {
            int b = 8 * bq + bi;
            *(float4*)&g_PX[((size_t)t * (NS * BB) + (w - 3) * BB + b) * 128 + c] =
                make_float4(acc[bi][0], acc[bi][1], acc[bi][2], acc[bi][3]);
        }
    }
}

// ---------------- sequential recurrence: 64 independent chains -------------
struct __align__(16) SeqSmem {
    __half2 dw[NS * 64 * PWD];   // 110592 B
    __half2 aw[192 * PWA];       // 104448 B
    __half2 h2[64];
    __half2 s2[192];
    __half2 agg2b[2 * SAGG];     // 2 buckets (parity of pair-row), 96 used
    __half2 sub2b[4 * SSUB];     // 4 buckets (pair-row mod 4), 48 used
    float   g[G3];
    float   tcv[128];
};

__device__ __forceinline__ float sigm_fast(float v) {
    return __fdividef(1.f, 1.f + __expf(-v));
}
__device__ __forceinline__ float tanh_fast(float v) {
    return 1.f - __fdividef(2.f, __expf(2.f * v) + 1.f);
}
__device__ __forceinline__ __half2 h2_of(unsigned u) {
    return *reinterpret_cast<__half2*>(&u);
}

// NBLK*16-element (NBLK*32-MAC) dot: 4 independent half2 chains,
// fp32 fold every 32 MACs. Weight element e at w[e*WS]; acts contiguous uint4.
template <int WS, int NBLK>
__device__ __forceinline__ float dot_h2(const __half2* __restrict__ w,
                                        const uint4* __restrict__ acts)
{
    float f0 = 0.f, f1 = 0.f;
    #pragma unroll
    for (int blk = 0; blk < NBLK; blk++) {
        __half2 z = __float2half2_rn(0.f);
        __half2 c0 = z, c1 = z, c2 = z, c3 = z;
        #pragma unroll
        for (int i = 0; i < 4; i++) {
            uint4 A = acts[4 * blk + i];
            const __half2* wp = w + (size_t)(16 * blk + 4 * i) * WS;
            c0 = __hfma2(wp[0],      h2_of(A.x), c0);
            c1 = __hfma2(wp[1 * WS], h2_of(A.y), c1);
            c2 = __hfma2(wp[2 * WS], h2_of(A.z), c2);
            c3 = __hfma2(wp[3 * WS], h2_of(A.w), c3);
        }
        __half2 sc = __hadd2(__hadd2(c0, c1), __hadd2(c2, c3));
        float2 ff = __half22float2(sc);
        f0 += ff.x;
        f1 += ff.y;
    }
    return f0 + f1;
}

__global__ void __launch_bounds__(768, 1) seq_kernel(
    const float* __restrict__ stk, const float* __restrict__ db,
    const float* __restrict__ ab, float* __restrict__ out)
{
    extern __shared__ char smem_raw[];
    SeqSmem& sh = *reinterpret_cast<SeqSmem*>(smem_raw);

    int tid = threadIdx.x;
    int b   = blockIdx.x;

    // stage-A mapping (gates || agg), validated in R10
    int grp  = tid / 384;               // 0: gates, 1: agg_in
    int t384 = tid - grp * 384;
    int kA   = t384 >> 7;
    int colA = t384 & 127;
    int rA   = 3 * b + kA;
    int nA   = rA >> 6;

    // stage-B mapping: thread = 2*o + p; p takes interleaved pair-rows p, p+2,...
    int oB   = tid >> 1;
    int pB   = tid & 1;
    int kB   = oB >> 7;
    int colB = oB & 127;
    int nB   = (3 * b + kB) >> 6;

    // stage-C mapping: thread = 4*j + p (tid<512); p takes pair-rows p, p+4,...
    int jC = tid >> 2;
    int pC = tid & 3;

    // bulk-copy SMEM-resident weights (dw, aw). uint4 = 4 half2 (16 B).
    {
        const uint4* src_dw = (const uint4*)g_dwp;
        const uint4* src_aw = (const uint4*)g_awp;
        uint4* dst_dw = (uint4*)sh.dw;
        uint4* dst_aw = (uint4*)sh.aw;
        for (int i = tid; i < (NS * 64 * PWD) / 4; i += 768) dst_dw[i] = src_dw[i];
        for (int i = tid; i < (192 * PWA) / 4;     i += 768) dst_aw[i] = src_aw[i];
    }
    // per-thread constants
    float db_r = db[nB * 128 + colB];
    float rh_r = stk[nB * 256 + colB];
    float rx_r = stk[nB * 256 + 128 + colB];
    float ab_r = (tid < 512) ? ab[jC] : 0.f;
    float s_reg = 0.f, c_reg = 0.f;

    if (tid < 64)  sh.h2[tid] = __float2half2_rn(0.f);
    if (tid < 192) sh.s2[tid] = __float2half2_rn(0.f);
    if (tid < 2 * SAGG) sh.agg2b[tid] = __float2half2_rn(0.f);
    if (tid < 4 * SSUB) sh.sub2b[tid] = __float2half2_rn(0.f);
    __syncthreads();

    // stage-A weight pointers (global streams)
    const __half2* Rp = g_Rh2 + t384;               // gates (grp0), stride G3
    const __half2* Sp = g_skh2 + nA * 8192 + colA;  // agg   (grp1), stride 128
    // stage-B weights (SMEM): interleaved rows pB+2e, element stride 2*PWD
    const __half2* Dp = sh.dw + nB * (64 * PWD) + pB * PWD + colB;
    // stage-C weights (SMEM): interleaved rows pC+4e, element stride 4*PWA
    const __half2* Ap = sh.aw + pC * PWA + jC;

    // x-term stream (stride per t is 24576 floats for both arrays)
    const float* xp = (grp == 0) ? (g_GX + (size_t)b * G3 + t384)
                                 : (g_PX + (size_t)rA * 128 + colA);
    float xt = __ldcs(xp);

    const uint4* hq  = (const uint4*)sh.h2;
    const uint4* sq  = (const uint4*)(sh.s2 + (kA << 6));
    const uint4* aqB = (const uint4*)(sh.agg2b + pB * SAGG + kB * 32);
    const uint4* bqC = (const uint4*)(sh.sub2b + pC * SSUB);

    for (int t = 0; t < TT; t++) {
        int tn = (t + 1 < TT) ? (t + 1) : t;
        float xtN = __ldcs(xp + (size_t)tn * 24576);

        // ---- stage A: gates (warps 0-11) || agg_in (warps 12-23)
        if (grp == 0) {
            float gdot = dot_h2<G3, 4>(Rp, hq);
            sh.g[t384] = sigm_fast(xt + gdot);
        } else {
            float edot = dot_h2<128, 4>(Sp, sq);
            float aggv = xt + edot;
            float aggp = __shfl_xor_sync(0xffffffffu, aggv, 1);
            if (!(colA & 1)) {
                int q = colA >> 1;              // within-k pair index 0..63
                sh.agg2b[(q & 1) * SAGG + kA * 32 + (q >> 1)] =
                    __floats2half2_rn(aggv, aggp);
            }
        }
        __syncthreads();

        // ---- stage B: dense (2-way interleaved split-K, shuffle combine)
        {
            float pv = dot_h2<2 * PWD, 2>(Dp, aqB);
            pv += __shfl_xor_sync(0xffffffffu, pv, 1);
            float so = fmaxf(pv + db_r, 0.f);
            s_reg = fmaf(rh_r, so, rx_r * s_reg);
            float so2 = __shfl_xor_sync(0xffffffffu, so, 2);
            float ss2 = __shfl_xor_sync(0xffffffffu, s_reg, 2);
            if (!(tid & 3)) {
                int q = oB >> 1;                // global pair index 0..191
                sh.sub2b[(q & 3) * SSUB + (q >> 2)] = __floats2half2_rn(so, so2);
                sh.s2[q] = __floats2half2_rn(s_reg, ss2);
            }
            if (tid < 128) {
                c_reg = fmaf(sh.g[128 + tid], c_reg,
                             sh.g[tid] * tanh_fast(sh.g[256 + tid]));
                sh.tcv[tid] = tanh_fast(c_reg);
            }
        }
        __syncthreads();

        // ---- stage C: agg_w (4-way interleaved split-K on tid<512) + h
        if (tid < 512) {
            float v = dot_h2<4 * PWA, 3>(Ap, bqC);
            v += __shfl_xor_sync(0xffffffffu, v, 1);
            v += __shfl_xor_sync(0xffffffffu, v, 2);
            float ov = sigm_fast(v + ab_r);
            float hv = ov * sh.tcv[jC];
            float hv2 = __shfl_xor_sync(0xffffffffu, hv, 4);
            if (!(tid & 3)) {
                if (!(tid & 7)) sh.h2[jC >> 1] = __floats2half2_rn(hv, hv2);
                __stcs(&out[((size_t)b * TT + t) * 128 + jC], hv);  // (B,T,U)
            }
        }
        xt = xtN;
        __syncthreads();
    }
}

// ---------------- launch ----------------------------------------------------
extern "C" void kernel_launch(void* const* d_in, const int* in_sizes, int n_in,
                              void* d_out, int out_size)
{
    const float* x    = (const float*)d_in[0];
    const float* K    = (const float*)d_in[1];
    const float* R    = (const float*)d_in[2];
    const float* bias = (const float*)d_in[3];
    const float* skx  = (const float*)d_in[4];
    const float* skh  = (const float*)d_in[5];
    const float* stk  = (const float*)d_in[6];
    const float* dw   = (const float*)d_in[7];
    const float* db   = (const float*)d_in[8];
    const float* aw   = (const float*)d_in[9];
    const float* ab   = (const float*)d_in[10];
    float* out = (float*)d_out;

    pack_weights<<<384, 256>>>(R, skh, dw, aw);

    dim3 pg(TT, 6);
    precompute_kernel<<<pg, 256>>>(x, K, skx, bias);

    cudaFuncSetAttribute(seq_kernel, cudaFuncAttributeMaxDynamicSharedMemorySize,
                         (int)sizeof(SeqSmem));
    seq_kernel<<<BB, 768, sizeof(SeqSmem)>>>(stk, db, ab, out);
}